// round 7
// baseline (speedup 1.0000x reference)
#include <cuda_runtime.h>
#include <cuda_bf16.h>
#include <cstdint>

#define NT 256
#define DD 256
#define NEG_BIG (-1e30f)
#define NSM 148

// ---- smem byte offsets (from 128B-aligned base) ----
#define QHI_OFF 0          // [64][256] bf16, 512B/row, swizzled
#define QLO_OFF 32768
#define KHI_OFF 65536      // [64][256] bf16 (K and V view of s2 tile)
#define KLO_OFF 98304
#define RAW_OFF 131072     // [64][256] f32 raw prefetch buffer (64KB)
#define PHI_OFF 196608     // [64][64] bf16, 128B/row, swizzled
#define PLO_OFF 204800
#define P1_OFF  212992     // 64 f32
#define P2_OFF  213248     // 64 f32
#define HM_OFF  213504     // [64][2] f32 half-maxes
#define HS_OFF  214016     // [64][2] f32 half-sums
#define U_OFF   214528     // unit broadcast word
#define SMEM_USED 214560
#define SMEM_BYTES (SMEM_USED + 128)

__device__ unsigned int g_unit_ctr;

__global__ void reset_ctr() { g_unit_ctr = 0u; }

__device__ __forceinline__ uint32_t smem_u32(const void* p) {
    uint32_t a;
    asm("{ .reg .u64 t; cvta.to.shared.u64 t, %1; cvt.u32.u64 %0, t; }"
        : "=r"(a) : "l"(p));
    return a;
}

#define CP_ASYNC16(dst, src) \
    asm volatile("cp.async.cg.shared.global [%0], [%1], 16;" \
        :: "r"(dst), "l"(src) : "memory")
#define CP_COMMIT() asm volatile("cp.async.commit_group;" ::: "memory")
#define CP_WAIT0()  asm volatile("cp.async.wait_group 0;" ::: "memory")

__device__ __forceinline__ void ldsm_x4(uint32_t& a0, uint32_t& a1, uint32_t& a2,
                                        uint32_t& a3, uint32_t addr) {
    asm volatile("ldmatrix.sync.aligned.m8n8.x4.shared.b16 {%0,%1,%2,%3}, [%4];"
                 : "=r"(a0), "=r"(a1), "=r"(a2), "=r"(a3) : "r"(addr));
}
__device__ __forceinline__ void ldsm_x4t(uint32_t& a0, uint32_t& a1, uint32_t& a2,
                                         uint32_t& a3, uint32_t addr) {
    asm volatile("ldmatrix.sync.aligned.m8n8.x4.trans.shared.b16 {%0,%1,%2,%3}, [%4];"
                 : "=r"(a0), "=r"(a1), "=r"(a2), "=r"(a3) : "r"(addr));
}
__device__ __forceinline__ void mma16816(float* c, uint32_t a0, uint32_t a1,
                                         uint32_t a2, uint32_t a3,
                                         uint32_t b0, uint32_t b1) {
    asm volatile(
        "mma.sync.aligned.m16n8k16.row.col.f32.bf16.bf16.f32 "
        "{%0,%1,%2,%3}, {%4,%5,%6,%7}, {%8,%9}, {%0,%1,%2,%3};"
        : "+f"(c[0]), "+f"(c[1]), "+f"(c[2]), "+f"(c[3])
        : "r"(a0), "r"(a1), "r"(a2), "r"(a3), "r"(b0), "r"(b1));
}

// swizzled chunk address: 16B chunks, XOR low-3 chunk bits with row&7
__device__ __forceinline__ uint32_t swz(int row, int chunk, int rowbytes) {
    int c = (chunk & ~7) | ((chunk & 7) ^ (row & 7));
    return (uint32_t)(row * rowbytes + c * 16);
}

// split 2 floats into packed bf16 hi + residual lo
__device__ __forceinline__ void split2(float a, float b, uint32_t& hi, uint32_t& lo) {
    __nv_bfloat16 ha = __float2bfloat16(a), hb = __float2bfloat16(b);
    float ra = a - __bfloat162float(ha), rb = b - __bfloat162float(hb);
    __nv_bfloat162 h; h.x = ha; h.y = hb;
    __nv_bfloat162 l; l.x = __float2bfloat16(ra); l.y = __float2bfloat16(rb);
    hi = *(uint32_t*)&h; lo = *(uint32_t*)&l;
}

__global__ void __launch_bounds__(NT, 1)
bidaf_mma(const float* __restrict__ s1, const float* __restrict__ s2,
          const float* __restrict__ w, const int* __restrict__ l1,
          const int* __restrict__ l2, float* __restrict__ out,
          int nunits, int B)
{
    extern __shared__ char sm_raw[];
    char* smc = (char*)(((uintptr_t)sm_raw + 127) & ~(uintptr_t)127);

    const int tid = threadIdx.x;
    const uint32_t smem = smem_u32(smc);
    const int lane = tid & 31;
    const int wid  = tid >> 5;
    const int rg   = wid >> 1;   // row group 0..3 (16 rows each)
    const int ch   = wid & 1;    // col half

    const float4* w1v = (const float4*)w;
    const float4* w2v = (const float4*)(w + DD);
    const float4* w3v = (const float4*)(w + 2 * DD);

    const int prow = tid >> 2, ph = tid & 3;   // prefetch/convert mapping

    float* hm = (float*)(smc + HM_OFF);
    float* hs = (float*)(smc + HS_OFF);
    const float4* rawv = (const float4*)(smc + RAW_OFF);
    volatile unsigned* uword = (volatile unsigned*)(smc + U_OFF);

    for (;;) {
        if (tid == 0) *uword = atomicAdd(&g_unit_ctr, 1u);
        __syncthreads();
        const unsigned u = *uword;
        if (u >= (unsigned)nunits) break;

        const int b  = (int)(u % (unsigned)B);
        const int m0 = (int)(u / (unsigned)B) * 64;
        const int L1v = l1[b], L2v = l2[b];
        float* outTile = out + ((size_t)b * 1024 + m0) * DD;

        if (m0 >= L1v || L2v == 0) {
            float4 z = make_float4(0.f, 0.f, 0.f, 0.f);
            for (int i = tid; i < 64 * DD / 4; i += NT) ((float4*)outTile)[i] = z;
            continue;
        }

        const float* s1b = s1 + ((size_t)b * 1024 + m0) * DD;
        const float* s2b = s2 + (size_t)b * 1024 * DD;

        // ---- prefetch tile 0 into RAW (overlaps the Q prologue below) ----
        {
            const char* src = (const char*)(s2b + (size_t)prow * DD);
            uint32_t dst = smem + RAW_OFF + (uint32_t)prow * 1024;
            #pragma unroll
            for (int i = 0; i < 16; i++) {
                int c = ph * 16 + i;
                CP_ASYNC16(dst + c * 16, src + c * 16);
            }
            CP_COMMIT();
        }

        // ------------- prologue: Q = s1*w3 -> bf16 hi/lo smem; part1 -------------
        {
            const float4* qr = (const float4*)(s1b + prow * DD);
            float acc = 0.f;
            #pragma unroll
            for (int cc = 0; cc < 8; cc++) {
                int c4 = ph * 16 + cc * 2;
                float4 v0 = qr[c4], v1 = qr[c4 + 1];
                float4 a0 = w1v[c4], a1 = w1v[c4 + 1];
                acc += v0.x * a0.x + v0.y * a0.y + v0.z * a0.z + v0.w * a0.w;
                acc += v1.x * a1.x + v1.y * a1.y + v1.z * a1.z + v1.w * a1.w;
                float4 m3a = w3v[c4], m3b = w3v[c4 + 1];
                float q0 = v0.x * m3a.x, q1 = v0.y * m3a.y, q2 = v0.z * m3a.z, q3 = v0.w * m3a.w;
                float q4 = v1.x * m3b.x, q5 = v1.y * m3b.y, q6 = v1.z * m3b.z, q7 = v1.w * m3b.w;
                uint4 hi, lo;
                split2(q0, q1, hi.x, lo.x); split2(q2, q3, hi.y, lo.y);
                split2(q4, q5, hi.z, lo.z); split2(q6, q7, hi.w, lo.w);
                uint32_t off = swz(prow, ph * 8 + cc, 512);
                *(uint4*)(smc + QHI_OFF + off) = hi;
                *(uint4*)(smc + QLO_OFF + off) = lo;
            }
            acc += __shfl_xor_sync(0xffffffffu, acc, 1);
            acc += __shfl_xor_sync(0xffffffffu, acc, 2);
            if (ph == 0) ((float*)(smc + P1_OFF))[prow] = acc;
        }
        __syncthreads();

        const int r0l = rg * 16 + (lane >> 2);   // c-frag rows
        const float p1a = ((const float*)(smc + P1_OFF))[r0l];
        const float p1b = ((const float*)(smc + P1_OFF))[r0l + 8];

        float O[16][4];
        #pragma unroll
        for (int j = 0; j < 16; j++)
            #pragma unroll
            for (int e = 0; e < 4; e++) O[j][e] = 0.f;
        float mrow0 = -INFINITY, mrow1 = -INFINITY, lrow0 = 0.f, lrow1 = 0.f;

        const int ntiles = (L2v + 63) >> 6;
        for (int t = 0; t < ntiles; t++) {
            const int n0 = t * 64;

            CP_WAIT0();
            __syncthreads();   // raw tile ready; prior PV done with K/P smem

            // ---- convert raw f32 -> K bf16 hi/lo; part2 ----
            {
                float acc = 0.f;
                #pragma unroll
                for (int cc = 0; cc < 8; cc++) {
                    int c4 = cc * 8 + ph * 2;            // bank-conflict-free read
                    float4 v0 = rawv[prow * 64 + c4], v1 = rawv[prow * 64 + c4 + 1];
                    float4 a0 = w2v[c4], a1 = w2v[c4 + 1];
                    acc += v0.x * a0.x + v0.y * a0.y + v0.z * a0.z + v0.w * a0.w;
                    acc += v1.x * a1.x + v1.y * a1.y + v1.z * a1.z + v1.w * a1.w;
                    uint4 hi, lo;
                    split2(v0.x, v0.y, hi.x, lo.x); split2(v0.z, v0.w, hi.y, lo.y);
                    split2(v1.x, v1.y, hi.z, lo.z); split2(v1.z, v1.w, hi.w, lo.w);
                    uint32_t off = swz(prow, cc * 4 + ph, 512);
                    *(uint4*)(smc + KHI_OFF + off) = hi;
                    *(uint4*)(smc + KLO_OFF + off) = lo;
                }
                acc += __shfl_xor_sync(0xffffffffu, acc, 1);
                acc += __shfl_xor_sync(0xffffffffu, acc, 2);
                if (ph == 0) ((float*)(smc + P2_OFF))[prow] = acc;
            }
            __syncthreads();   // K hi/lo + P2 ready; raw consumed

            // ---- prefetch next tile ----
            if (t + 1 < ntiles) {
                const char* src = (const char*)(s2b + (size_t)(n0 + 64 + prow) * DD);
                uint32_t dst = smem + RAW_OFF + (uint32_t)prow * 1024;
                #pragma unroll
                for (int i = 0; i < 16; i++) {
                    int c = ph * 16 + i;
                    CP_ASYNC16(dst + c * 16, src + c * 16);
                }
                CP_COMMIT();
            }

            // ---- score GEMM: S[16 rows][32 cols] per warp, 3-term bf16 split ----
            float c[4][4];
            #pragma unroll
            for (int j = 0; j < 4; j++)
                #pragma unroll
                for (int e = 0; e < 4; e++) c[j][e] = 0.f;

            const int arow = rg * 16 + (lane & 15);
            const int brow = ch * 32 + (lane & 7) + ((lane >> 4) & 1) * 8;
            #pragma unroll 4
            for (int k16 = 0; k16 < 16; k16++) {
                uint32_t aoff = swz(arow, 2 * k16 + (lane >> 4), 512);
                uint32_t ah0, ah1, ah2, ah3, al0, al1, al2, al3;
                ldsm_x4(ah0, ah1, ah2, ah3, smem + QHI_OFF + aoff);
                ldsm_x4(al0, al1, al2, al3, smem + QLO_OFF + aoff);
                #pragma unroll
                for (int jp = 0; jp < 2; jp++) {
                    uint32_t boff = swz(brow + jp * 16, 2 * k16 + ((lane >> 3) & 1), 512);
                    uint32_t bh0, bh1, bh2, bh3, bl0, bl1, bl2, bl3;
                    ldsm_x4(bh0, bh1, bh2, bh3, smem + KHI_OFF + boff);
                    ldsm_x4(bl0, bl1, bl2, bl3, smem + KLO_OFF + boff);
                    mma16816(c[2 * jp], ah0, ah1, ah2, ah3, bh0, bh1);
                    mma16816(c[2 * jp + 1], ah0, ah1, ah2, ah3, bh2, bh3);
                    mma16816(c[2 * jp], ah0, ah1, ah2, ah3, bl0, bl1);
                    mma16816(c[2 * jp + 1], ah0, ah1, ah2, ah3, bl2, bl3);
                    mma16816(c[2 * jp], al0, al1, al2, al3, bh0, bh1);
                    mma16816(c[2 * jp + 1], al0, al1, al2, al3, bh2, bh3);
                }
            }

            // ---- bias + mask + row max ----
            const float* p2f = (const float*)(smc + P2_OFF);
            float mx0 = -INFINITY, mx1 = -INFINITY;
            #pragma unroll
            for (int j = 0; j < 4; j++) {
                #pragma unroll
                for (int e = 0; e < 2; e++) {
                    int col = ch * 32 + j * 8 + 2 * (lane & 3) + e;
                    bool valid = (n0 + col) < L2v;
                    float bias = p2f[col];
                    float s0 = c[j][e] + p1a + bias;
                    float s1v = c[j][e + 2] + p1b + bias;
                    s0 = valid ? s0 : NEG_BIG;
                    s1v = valid ? s1v : NEG_BIG;
                    c[j][e] = s0; c[j][e + 2] = s1v;
                    mx0 = fmaxf(mx0, s0); mx1 = fmaxf(mx1, s1v);
                }
            }
            mx0 = fmaxf(mx0, __shfl_xor_sync(0xffffffffu, mx0, 1));
            mx0 = fmaxf(mx0, __shfl_xor_sync(0xffffffffu, mx0, 2));
            mx1 = fmaxf(mx1, __shfl_xor_sync(0xffffffffu, mx1, 1));
            mx1 = fmaxf(mx1, __shfl_xor_sync(0xffffffffu, mx1, 2));
            if ((lane & 3) == 0) {
                hm[r0l * 2 + ch] = mx0;
                hm[(r0l + 8) * 2 + ch] = mx1;
            }
            __syncthreads();

            const float tm0 = fmaxf(hm[r0l * 2], hm[r0l * 2 + 1]);
            const float tm1 = fmaxf(hm[(r0l + 8) * 2], hm[(r0l + 8) * 2 + 1]);
            const float mnew0 = fmaxf(mrow0, tm0), mnew1 = fmaxf(mrow1, tm1);
            const float alpha0 = __expf(mrow0 - mnew0), alpha1 = __expf(mrow1 - mnew1);
            mrow0 = mnew0; mrow1 = mnew1;

            float sum0 = 0.f, sum1 = 0.f;
            #pragma unroll
            for (int j = 0; j < 4; j++) {
                float p00 = __expf(c[j][0] - mnew0), p01 = __expf(c[j][1] - mnew0);
                float p10 = __expf(c[j][2] - mnew1), p11 = __expf(c[j][3] - mnew1);
                sum0 += p00 + p01; sum1 += p10 + p11;
                int nloc = ch * 32 + j * 8 + 2 * (lane & 3);
                int chunk = nloc >> 3;
                uint32_t hi, lo;
                uint32_t off0 = (uint32_t)(r0l * 128 + ((chunk ^ (r0l & 7)) * 16) + (nloc & 7) * 2);
                split2(p00, p01, hi, lo);
                *(uint32_t*)(smc + PHI_OFF + off0) = hi;
                *(uint32_t*)(smc + PLO_OFF + off0) = lo;
                int r1 = r0l + 8;
                uint32_t off1 = (uint32_t)(r1 * 128 + ((chunk ^ (r1 & 7)) * 16) + (nloc & 7) * 2);
                split2(p10, p11, hi, lo);
                *(uint32_t*)(smc + PHI_OFF + off1) = hi;
                *(uint32_t*)(smc + PLO_OFF + off1) = lo;
            }
            sum0 += __shfl_xor_sync(0xffffffffu, sum0, 1);
            sum0 += __shfl_xor_sync(0xffffffffu, sum0, 2);
            sum1 += __shfl_xor_sync(0xffffffffu, sum1, 1);
            sum1 += __shfl_xor_sync(0xffffffffu, sum1, 2);
            if ((lane & 3) == 0) {
                hs[r0l * 2 + ch] = sum0;
                hs[(r0l + 8) * 2 + ch] = sum1;
            }

            // rescale O while sums land
            #pragma unroll
            for (int j = 0; j < 16; j++) {
                O[j][0] *= alpha0; O[j][1] *= alpha0;
                O[j][2] *= alpha1; O[j][3] *= alpha1;
            }
            __syncthreads();

            lrow0 = lrow0 * alpha0 + hs[r0l * 2] + hs[r0l * 2 + 1];
            lrow1 = lrow1 * alpha1 + hs[(r0l + 8) * 2] + hs[(r0l + 8) * 2 + 1];

            // ---- PV GEMM: O[16 rows][128 d] += P[16][64] * V[64][128] ----
            #pragma unroll
            for (int ks = 0; ks < 4; ks++) {
                uint32_t aoff = swz(rg * 16 + (lane & 15), 2 * ks + (lane >> 4), 128);
                uint32_t ph0, ph1, ph2, ph3, pl0, pl1, pl2, pl3;
                ldsm_x4(ph0, ph1, ph2, ph3, smem + PHI_OFF + aoff);
                ldsm_x4(pl0, pl1, pl2, pl3, smem + PLO_OFF + aoff);
                const int vrow = ks * 16 + (lane & 15);
                #pragma unroll
                for (int jp = 0; jp < 8; jp++) {
                    uint32_t boff = swz(vrow, ch * 16 + 2 * jp + (lane >> 4), 512);
                    uint32_t vh0, vh1, vh2, vh3, vl0, vl1, vl2, vl3;
                    ldsm_x4t(vh0, vh1, vh2, vh3, smem + KHI_OFF + boff);
                    ldsm_x4t(vl0, vl1, vl2, vl3, smem + KLO_OFF + boff);
                    mma16816(O[2 * jp], ph0, ph1, ph2, ph3, vh0, vh1);
                    mma16816(O[2 * jp + 1], ph0, ph1, ph2, ph3, vh2, vh3);
                    mma16816(O[2 * jp], ph0, ph1, ph2, ph3, vl0, vl1);
                    mma16816(O[2 * jp + 1], ph0, ph1, ph2, ph3, vl2, vl3);
                    mma16816(O[2 * jp], pl0, pl1, pl2, pl3, vh0, vh1);
                    mma16816(O[2 * jp + 1], pl0, pl1, pl2, pl3, vh2, vh3);
                }
            }
        }

        // ---------------- epilogue ----------------
        const int gr0 = m0 + r0l, gr1 = gr0 + 8;
        const float inv0 = (gr0 < L1v) ? (1.f / lrow0) : 0.f;
        const float inv1 = (gr1 < L1v) ? (1.f / lrow1) : 0.f;
        float* orow0 = outTile + r0l * DD + ch * 128 + 2 * (lane & 3);
        float* orow1 = orow0 + 8 * DD;
        #pragma unroll
        for (int j = 0; j < 16; j++) {
            float2 v0; v0.x = O[j][0] * inv0; v0.y = O[j][1] * inv0;
            float2 v1; v1.x = O[j][2] * inv1; v1.y = O[j][3] * inv1;
            *(float2*)(orow0 + j * 8) = v0;
            *(float2*)(orow1 + j * 8) = v1;
        }
    }
}

extern "C" void kernel_launch(void* const* d_in, const int* in_sizes, int n_in,
                              void* d_out, int out_size)
{
    const float* s1 = (const float*)d_in[0];
    const float* s2 = (const float*)d_in[1];
    const float* w  = (const float*)d_in[2];
    const int*   l1 = (const int*)d_in[3];
    const int*   l2 = (const int*)d_in[4];
    float* out = (float*)d_out;

    const int B  = in_sizes[3];
    const int D  = in_sizes[2] / 3;
    const int t1 = in_sizes[0] / (B * D);
    const int nunits = (t1 / 64) * B;

    cudaFuncSetAttribute(bidaf_mma, cudaFuncAttributeMaxDynamicSharedMemorySize,
                         SMEM_BYTES);
    reset_ctr<<<1, 1>>>();
    bidaf_mma<<<NSM, NT, SMEM_BYTES>>>(s1, s2, w, l1, l2, out, nunits, B);
}

// round 8
// speedup vs baseline: 1.4007x; 1.4007x over previous
#include <cuda_runtime.h>
#include <cuda_bf16.h>
#include <cstdint>

#define NT 256
#define DD 256
#define NEG_BIG (-1e30f)

// ---- smem byte offsets (from 128B-aligned base) ----
#define QHI_OFF 0          // [128][256] bf16 hi, 512B/row, swizzled
#define QLO_OFF 65536      // [128][256] bf16 lo
#define KHI_OFF 131072     // [64][256] bf16 hi (K and V view of s2 tile)
#define KLO_OFF 163840
#define RAW_OFF 196608     // [32][256] f32 staging (half tile)
#define P1_OFF  229376     // 128 f32
#define P2_OFF  229888     // 64 f32
#define SMEM_USED 230144
#define SMEM_BYTES (SMEM_USED + 128)

__device__ __forceinline__ uint32_t smem_u32(const void* p) {
    uint32_t a;
    asm("{ .reg .u64 t; cvta.to.shared.u64 t, %1; cvt.u32.u64 %0, t; }"
        : "=r"(a) : "l"(p));
    return a;
}

#define CP_ASYNC16(dst, src) \
    asm volatile("cp.async.cg.shared.global [%0], [%1], 16;" \
        :: "r"(dst), "l"(src) : "memory")
#define CP_COMMIT() asm volatile("cp.async.commit_group;" ::: "memory")
#define CP_WAIT0()  asm volatile("cp.async.wait_group 0;" ::: "memory")

__device__ __forceinline__ void ldsm_x4(uint32_t& a0, uint32_t& a1, uint32_t& a2,
                                        uint32_t& a3, uint32_t addr) {
    asm volatile("ldmatrix.sync.aligned.m8n8.x4.shared.b16 {%0,%1,%2,%3}, [%4];"
                 : "=r"(a0), "=r"(a1), "=r"(a2), "=r"(a3) : "r"(addr));
}
__device__ __forceinline__ void ldsm_x4t(uint32_t& a0, uint32_t& a1, uint32_t& a2,
                                         uint32_t& a3, uint32_t addr) {
    asm volatile("ldmatrix.sync.aligned.m8n8.x4.trans.shared.b16 {%0,%1,%2,%3}, [%4];"
                 : "=r"(a0), "=r"(a1), "=r"(a2), "=r"(a3) : "r"(addr));
}
__device__ __forceinline__ void mma16816(float* c, uint32_t a0, uint32_t a1,
                                         uint32_t a2, uint32_t a3,
                                         uint32_t b0, uint32_t b1) {
    asm volatile(
        "mma.sync.aligned.m16n8k16.row.col.f32.bf16.bf16.f32 "
        "{%0,%1,%2,%3}, {%4,%5,%6,%7}, {%8,%9}, {%0,%1,%2,%3};"
        : "+f"(c[0]), "+f"(c[1]), "+f"(c[2]), "+f"(c[3])
        : "r"(a0), "r"(a1), "r"(a2), "r"(a3), "r"(b0), "r"(b1));
}

// swizzled chunk address: 16B chunks, XOR low-3 chunk bits with row&7
__device__ __forceinline__ uint32_t swz(int row, int chunk, int rowbytes) {
    int c = (chunk & ~7) | ((chunk & 7) ^ (row & 7));
    return (uint32_t)(row * rowbytes + c * 16);
}

__device__ __forceinline__ uint32_t pk2(__nv_bfloat16 a, __nv_bfloat16 b) {
    __nv_bfloat162 t; t.x = a; t.y = b;
    return *reinterpret_cast<uint32_t*>(&t);
}

// split 2 floats into packed bf16 hi + residual lo
__device__ __forceinline__ void split2(float a, float b, uint32_t& hi, uint32_t& lo) {
    __nv_bfloat16 ha = __float2bfloat16(a), hb = __float2bfloat16(b);
    float ra = a - __bfloat162float(ha), rb = b - __bfloat162float(hb);
    hi = pk2(ha, hb);
    lo = pk2(__float2bfloat16(ra), __float2bfloat16(rb));
}

__global__ void __launch_bounds__(NT, 1)
bidaf_fa2(const float* __restrict__ s1, const float* __restrict__ s2,
          const float* __restrict__ w, const int* __restrict__ l1,
          const int* __restrict__ l2, float* __restrict__ out)
{
    extern __shared__ char sm_raw[];
    char* smc = (char*)(((uintptr_t)sm_raw + 127) & ~(uintptr_t)127);

    const int b   = blockIdx.y;
    const int m0  = blockIdx.x * 128;
    const int tid = threadIdx.x;
    const int L1v = l1[b], L2v = l2[b];
    float* outTile = out + ((size_t)b * 1024 + m0) * DD;

    if (m0 >= L1v || L2v == 0) {
        float4 z = make_float4(0.f, 0.f, 0.f, 0.f);
        for (int i = tid; i < 128 * DD / 4; i += NT) ((float4*)outTile)[i] = z;
        return;
    }

    const uint32_t smem = smem_u32(smc);
    const int lane = tid & 31;
    const int wid  = tid >> 5;

    const float* s1b = s1 + ((size_t)b * 1024 + m0) * DD;
    const float* s2b = s2 + (size_t)b * 1024 * DD;
    const float4* w1v = (const float4*)w;
    const float4* w2v = (const float4*)(w + DD);
    const float4* w3v = (const float4*)(w + 2 * DD);

    const int crow = tid >> 3, chh = tid & 7;   // convert mapping: 8 threads/row

    // ---- issue gA(tile0, rows 0-31) into RAW ----
    {
        const char* src = (const char*)(s2b + (size_t)crow * DD);
        uint32_t dst = smem + RAW_OFF + (uint32_t)crow * 1024;
        #pragma unroll
        for (int p = 0; p < 8; p++) {
            int c4 = chh + 8 * p;
            CP_ASYNC16(dst + c4 * 16, src + c4 * 16);
        }
        CP_COMMIT();
    }

    // ---------------- prologue: Q = s1*w3 -> bf16 hi/lo smem; part1 ----------------
    {
        const int row = tid >> 1, h = tid & 1;
        const float4* qr = (const float4*)(s1b + row * DD);
        float acc = 0.f;
        #pragma unroll
        for (int i = 0; i < 32; i++) {
            int c4 = 2 * i + h;
            float4 v = qr[c4];
            float4 a1 = w1v[c4];
            acc += v.x * a1.x + v.y * a1.y + v.z * a1.z + v.w * a1.w;
            float4 m3 = w3v[c4];
            float q0 = v.x * m3.x, q1 = v.y * m3.y, q2 = v.z * m3.z, q3 = v.w * m3.w;
            uint32_t hA, lA, hB, lB;
            split2(q0, q1, hA, lA); split2(q2, q3, hB, lB);
            uint32_t off = swz(row, i, 512) + h * 8;
            *(uint2*)(smc + QHI_OFF + off) = make_uint2(hA, hB);
            *(uint2*)(smc + QLO_OFF + off) = make_uint2(lA, lB);
        }
        acc += __shfl_xor_sync(0xffffffffu, acc, 1);
        if (h == 0) ((float*)(smc + P1_OFF))[row] = acc;
    }
    __syncthreads();

    const int r0l = wid * 16 + (lane >> 2);     // this thread's c-frag row (and +8)
    const float p1a = ((const float*)(smc + P1_OFF))[r0l];
    const float p1b = ((const float*)(smc + P1_OFF))[r0l + 8];
    const int lam = lane & 3;                   // lambda: col pair owner

    float O[32][4];
    #pragma unroll
    for (int j = 0; j < 32; j++)
        #pragma unroll
        for (int e = 0; e < 4; e++) O[j][e] = 0.f;
    float mrow0 = -INFINITY, mrow1 = -INFINITY, lrow0 = 0.f, lrow1 = 0.f;

    const float4* rawv = (const float4*)(smc + RAW_OFF);
    const float* p2f = (const float*)(smc + P2_OFF);

    const int arow = wid * 16 + (lane & 15);
    const int brow = (lane & 7) + ((lane >> 4) & 1) * 8;

    const int ntiles = (L2v + 63) >> 6;
    for (int t = 0; t < ntiles; t++) {
        const int n0 = t * 64;

        __syncthreads();       // prior PV done reading K
        CP_WAIT0();            // gA(t): rows n0..n0+31 staged

        // ---- convert half0 (K rows 0-31 of tile) + part2; then issue gB ----
        {
            float acc = 0.f;
            const float4* slot = rawv + crow * 64;
            #pragma unroll
            for (int p = 0; p < 8; p++) {
                int c4 = chh + 8 * p;
                float4 v = slot[c4];
                float4 a2 = w2v[c4];
                acc += v.x * a2.x + v.y * a2.y + v.z * a2.z + v.w * a2.w;
                uint32_t hA, lA, hB, lB;
                split2(v.x, v.y, hA, lA); split2(v.z, v.w, hB, lB);
                uint32_t off = swz(crow, c4 >> 1, 512) + (c4 & 1) * 8;
                *(uint2*)(smc + KHI_OFF + off) = make_uint2(hA, hB);
                *(uint2*)(smc + KLO_OFF + off) = make_uint2(lA, lB);
            }
            acc += __shfl_xor_sync(0xffffffffu, acc, 1);
            acc += __shfl_xor_sync(0xffffffffu, acc, 2);
            acc += __shfl_xor_sync(0xffffffffu, acc, 4);
            if (chh == 0) ((float*)(smc + P2_OFF))[crow] = acc;
            // issue gB: rows n0+32..n0+63 (this thread's slot just consumed)
            const char* src = (const char*)(s2b + (size_t)(n0 + 32 + crow) * DD);
            uint32_t dst = smem + RAW_OFF + (uint32_t)crow * 1024;
            #pragma unroll
            for (int p = 0; p < 8; p++) {
                int c4 = chh + 8 * p;
                CP_ASYNC16(dst + c4 * 16, src + c4 * 16);
            }
            CP_COMMIT();
        }
        __syncthreads();       // K rows 0-31 + P2[0..31] visible

        // ---- score phase A: n-cols 0-31 (c[0..3]) ----
        float c[8][4];
        #pragma unroll
        for (int j = 0; j < 8; j++)
            #pragma unroll
            for (int e = 0; e < 4; e++) c[j][e] = 0.f;

        #pragma unroll 4
        for (int k = 0; k < 16; k++) {
            uint32_t aoff = swz(arow, 2 * k + (lane >> 4), 512);
            uint32_t ah0, ah1, ah2, ah3, al0, al1, al2, al3;
            ldsm_x4(ah0, ah1, ah2, ah3, smem + QHI_OFF + aoff);
            ldsm_x4(al0, al1, al2, al3, smem + QLO_OFF + aoff);
            #pragma unroll
            for (int nb = 0; nb < 2; nb++) {
                uint32_t boff = swz(brow + nb * 16, 2 * k + ((lane >> 3) & 1), 512);
                uint32_t bh0, bh1, bh2, bh3, bl0, bl1, bl2, bl3;
                ldsm_x4(bh0, bh1, bh2, bh3, smem + KHI_OFF + boff);
                ldsm_x4(bl0, bl1, bl2, bl3, smem + KLO_OFF + boff);
                mma16816(c[2 * nb], ah0, ah1, ah2, ah3, bh0, bh1);
                mma16816(c[2 * nb + 1], ah0, ah1, ah2, ah3, bh2, bh3);
                mma16816(c[2 * nb], ah0, ah1, ah2, ah3, bl0, bl1);
                mma16816(c[2 * nb + 1], ah0, ah1, ah2, ah3, bl2, bl3);
                mma16816(c[2 * nb], al0, al1, al2, al3, bh0, bh1);
                mma16816(c[2 * nb + 1], al0, al1, al2, al3, bh2, bh3);
            }
        }

        CP_WAIT0();            // gB landed (covered by score phase A)

        // ---- convert half1 (K rows 32-63) + part2; issue gA(t+1) ----
        {
            float acc = 0.f;
            const int krow = 32 + crow;
            const float4* slot = rawv + crow * 64;
            #pragma unroll
            for (int p = 0; p < 8; p++) {
                int c4 = chh + 8 * p;
                float4 v = slot[c4];
                float4 a2 = w2v[c4];
                acc += v.x * a2.x + v.y * a2.y + v.z * a2.z + v.w * a2.w;
                uint32_t hA, lA, hB, lB;
                split2(v.x, v.y, hA, lA); split2(v.z, v.w, hB, lB);
                uint32_t off = swz(krow, c4 >> 1, 512) + (c4 & 1) * 8;
                *(uint2*)(smc + KHI_OFF + off) = make_uint2(hA, hB);
                *(uint2*)(smc + KLO_OFF + off) = make_uint2(lA, lB);
            }
            acc += __shfl_xor_sync(0xffffffffu, acc, 1);
            acc += __shfl_xor_sync(0xffffffffu, acc, 2);
            acc += __shfl_xor_sync(0xffffffffu, acc, 4);
            if (chh == 0) ((float*)(smc + P2_OFF))[krow] = acc;
            if (t + 1 < ntiles) {
                const char* src = (const char*)(s2b + (size_t)(n0 + 64 + crow) * DD);
                uint32_t dst = smem + RAW_OFF + (uint32_t)crow * 1024;
                #pragma unroll
                for (int p = 0; p < 8; p++) {
                    int c4 = chh + 8 * p;
                    CP_ASYNC16(dst + c4 * 16, src + c4 * 16);
                }
                CP_COMMIT();
            }
        }
        __syncthreads();       // K rows 32-63 + P2[32..63] visible

        // ---- score phase B: n-cols 32-63 (c[4..7]) ----
        #pragma unroll 4
        for (int k = 0; k < 16; k++) {
            uint32_t aoff = swz(arow, 2 * k + (lane >> 4), 512);
            uint32_t ah0, ah1, ah2, ah3, al0, al1, al2, al3;
            ldsm_x4(ah0, ah1, ah2, ah3, smem + QHI_OFF + aoff);
            ldsm_x4(al0, al1, al2, al3, smem + QLO_OFF + aoff);
            #pragma unroll
            for (int nb = 0; nb < 2; nb++) {
                uint32_t boff = swz(brow + 32 + nb * 16, 2 * k + ((lane >> 3) & 1), 512);
                uint32_t bh0, bh1, bh2, bh3, bl0, bl1, bl2, bl3;
                ldsm_x4(bh0, bh1, bh2, bh3, smem + KHI_OFF + boff);
                ldsm_x4(bl0, bl1, bl2, bl3, smem + KLO_OFF + boff);
                mma16816(c[4 + 2 * nb], ah0, ah1, ah2, ah3, bh0, bh1);
                mma16816(c[5 + 2 * nb], ah0, ah1, ah2, ah3, bh2, bh3);
                mma16816(c[4 + 2 * nb], ah0, ah1, ah2, ah3, bl0, bl1);
                mma16816(c[5 + 2 * nb], ah0, ah1, ah2, ah3, bl2, bl3);
                mma16816(c[4 + 2 * nb], al0, al1, al2, al3, bh0, bh1);
                mma16816(c[5 + 2 * nb], al0, al1, al2, al3, bh2, bh3);
            }
        }

        // ---- warp-local softmax: bias + mask + max + exp + sum ----
        float mx0 = -INFINITY, mx1 = -INFINITY;
        #pragma unroll
        for (int j = 0; j < 8; j++) {
            #pragma unroll
            for (int e = 0; e < 2; e++) {
                int col = j * 8 + 2 * lam + e;
                bool valid = (n0 + col) < L2v;
                float bias = p2f[col];
                float s0 = c[j][e] + p1a + bias;
                float s1v = c[j][e + 2] + p1b + bias;
                s0 = valid ? s0 : NEG_BIG;
                s1v = valid ? s1v : NEG_BIG;
                c[j][e] = s0; c[j][e + 2] = s1v;
                mx0 = fmaxf(mx0, s0); mx1 = fmaxf(mx1, s1v);
            }
        }
        mx0 = fmaxf(mx0, __shfl_xor_sync(0xffffffffu, mx0, 1));
        mx0 = fmaxf(mx0, __shfl_xor_sync(0xffffffffu, mx0, 2));
        mx1 = fmaxf(mx1, __shfl_xor_sync(0xffffffffu, mx1, 1));
        mx1 = fmaxf(mx1, __shfl_xor_sync(0xffffffffu, mx1, 2));

        const float mnew0 = fmaxf(mrow0, mx0), mnew1 = fmaxf(mrow1, mx1);
        const float alpha0 = __expf(mrow0 - mnew0), alpha1 = __expf(mrow1 - mnew1);
        mrow0 = mnew0; mrow1 = mnew1;

        float sum0 = 0.f, sum1 = 0.f;
        #pragma unroll
        for (int j = 0; j < 8; j++) {
            c[j][0] = __expf(c[j][0] - mnew0);
            c[j][1] = __expf(c[j][1] - mnew0);
            c[j][2] = __expf(c[j][2] - mnew1);
            c[j][3] = __expf(c[j][3] - mnew1);
            sum0 += c[j][0] + c[j][1];
            sum1 += c[j][2] + c[j][3];
        }
        sum0 += __shfl_xor_sync(0xffffffffu, sum0, 1);
        sum0 += __shfl_xor_sync(0xffffffffu, sum0, 2);
        sum1 += __shfl_xor_sync(0xffffffffu, sum1, 1);
        sum1 += __shfl_xor_sync(0xffffffffu, sum1, 2);
        lrow0 = lrow0 * alpha0 + sum0;
        lrow1 = lrow1 * alpha1 + sum1;

        // ---- pack P c-frags into PV a-frags (in registers) ----
        uint32_t pah[16], pal[16];
        #pragma unroll
        for (int kk = 0; kk < 4; kk++) {
            const int J = 2 * kk;
            split2(c[J][0],     c[J][1],     pah[4 * kk + 0], pal[4 * kk + 0]);
            split2(c[J][2],     c[J][3],     pah[4 * kk + 1], pal[4 * kk + 1]);
            split2(c[J + 1][0], c[J + 1][1], pah[4 * kk + 2], pal[4 * kk + 2]);
            split2(c[J + 1][2], c[J + 1][3], pah[4 * kk + 3], pal[4 * kk + 3]);
        }

        // ---- rescale O ----
        #pragma unroll
        for (int j = 0; j < 32; j++) {
            O[j][0] *= alpha0; O[j][1] *= alpha0;
            O[j][2] *= alpha1; O[j][3] *= alpha1;
        }

        // ---- PV: O[16 rows][256 d] += P[16][64] * V[64][256] ----
        #pragma unroll
        for (int kk = 0; kk < 4; kk++) {
            const int vrow = kk * 16 + (lane & 15);
            const uint32_t a0 = pah[4 * kk], a1 = pah[4 * kk + 1],
                           a2 = pah[4 * kk + 2], a3 = pah[4 * kk + 3];
            const uint32_t b0 = pal[4 * kk], b1 = pal[4 * kk + 1],
                           b2 = pal[4 * kk + 2], b3 = pal[4 * kk + 3];
            #pragma unroll
            for (int dblk = 0; dblk < 16; dblk++) {
                uint32_t boff = swz(vrow, 2 * dblk + (lane >> 4), 512);
                uint32_t vh0, vh1, vh2, vh3, vl0, vl1, vl2, vl3;
                ldsm_x4t(vh0, vh1, vh2, vh3, smem + KHI_OFF + boff);
                ldsm_x4t(vl0, vl1, vl2, vl3, smem + KLO_OFF + boff);
                mma16816(O[2 * dblk],     a0, a1, a2, a3, vh0, vh1);
                mma16816(O[2 * dblk + 1], a0, a1, a2, a3, vh2, vh3);
                mma16816(O[2 * dblk],     a0, a1, a2, a3, vl0, vl1);
                mma16816(O[2 * dblk + 1], a0, a1, a2, a3, vl2, vl3);
                mma16816(O[2 * dblk],     b0, b1, b2, b3, vh0, vh1);
                mma16816(O[2 * dblk + 1], b0, b1, b2, b3, vh2, vh3);
            }
        }
    }

    // ---------------- epilogue ----------------
    const int gr0 = m0 + r0l, gr1 = gr0 + 8;
    const float inv0 = (gr0 < L1v) ? (1.f / lrow0) : 0.f;
    const float inv1 = (gr1 < L1v) ? (1.f / lrow1) : 0.f;
    float* orow0 = outTile + r0l * DD + 2 * lam;
    float* orow1 = orow0 + 8 * DD;
    #pragma unroll
    for (int j = 0; j < 32; j++) {
        float2 v0; v0.x = O[j][0] * inv0; v0.y = O[j][1] * inv0;
        float2 v1; v1.x = O[j][2] * inv1; v1.y = O[j][3] * inv1;
        *(float2*)(orow0 + j * 8) = v0;
        *(float2*)(orow1 + j * 8) = v1;
    }
}

extern "C" void kernel_launch(void* const* d_in, const int* in_sizes, int n_in,
                              void* d_out, int out_size)
{
    const float* s1 = (const float*)d_in[0];
    const float* s2 = (const float*)d_in[1];
    const float* w  = (const float*)d_in[2];
    const int*   l1 = (const int*)d_in[3];
    const int*   l2 = (const int*)d_in[4];
    float* out = (float*)d_out;

    const int B  = in_sizes[3];
    const int D  = in_sizes[2] / 3;
    const int t1 = in_sizes[0] / (B * D);

    cudaFuncSetAttribute(bidaf_fa2, cudaFuncAttributeMaxDynamicSharedMemorySize,
                         SMEM_BYTES);
    dim3 grid(t1 / 128, B);
    bidaf_fa2<<<grid, NT, SMEM_BYTES>>>(s1, s2, w, l1, l2, out);
}